// round 2
// baseline (speedup 1.0000x reference)
#include <cuda_runtime.h>
#include <math.h>

#define BSZ   8
#define NA    256
#define BN    (BSZ*NA)     // 2048
#define LN    12
#define DI    27
#define HD    128
#define NACT  8

// scratch (static device allocations are allowed)
__device__ float g_agg[BN*HD];
__device__ float g_hg [BN*HD];
__device__ float g_ai [BN*HD];
__device__ float g_aj [BN*HD];

__device__ __forceinline__ float sigmoidf_(float x) { return 1.0f/(1.0f+expf(-x)); }

// ---------------------------------------------------------------------------
// Kernel A: lane encoder + GRU + lane attention + per-node graph pre-GEMVs
// one block per (batch*agent), 128 threads (thread t owns hidden channel t)
// ---------------------------------------------------------------------------
__global__ void __launch_bounds__(128) lane_kernel(
    const float* __restrict__ LF,      // (BN, LN, DI)
    const float* __restrict__ Hin,     // (BN*LN, HD)
    const float* __restrict__ fc1_w,   // (HD, DI)
    const float* __restrict__ fc1_b,   // (HD)
    const float* __restrict__ w_ih,    // (3HD, HD)
    const float* __restrict__ w_hh,    // (3HD, HD)
    const float* __restrict__ b_ih,    // (3HD)
    const float* __restrict__ b_hh,    // (3HD)
    const float* __restrict__ lattn_w, // (DI+HD)
    const float* __restrict__ lattn_b, // (1)
    const float* __restrict__ gfc_w,   // (HD, HD)
    const float* __restrict__ gfc_b,   // (HD)
    const float* __restrict__ ga1_w,   // (HD, 2HD)
    const float* __restrict__ ga1_b)   // (HD)
{
    const int bn   = blockIdx.x;
    const int t    = threadIdx.x;      // 0..127
    const int lane = t & 31;
    const int warp = t >> 5;

    __shared__ float sLF[LN][DI+1];
    __shared__ float sx [LN][HD];
    __shared__ float sh [LN][HD];
    __shared__ float sred[4*LN];
    __shared__ float swt[LN];
    __shared__ float sagg[HD];
    __shared__ float shg [HD];

    // ---- load lane features + hidden state ----
    const float* lf  = LF  + (size_t)bn * LN * DI;
    for (int i = t; i < LN*DI; i += 128) sLF[i/DI][i%DI] = lf[i];
    const float* hin = Hin + (size_t)bn * LN * HD;
    for (int i = t; i < LN*HD; i += 128) sh[i/HD][i%HD] = hin[i];
    __syncthreads();

    // ---- x = relu(LF @ fc1_w^T + fc1_b) ----
    {
        float wv[DI];
        #pragma unroll
        for (int d = 0; d < DI; d++) wv[d] = fc1_w[t*DI + d];
        const float bb = fc1_b[t];
        #pragma unroll
        for (int l = 0; l < LN; l++) {
            float acc = bb;
            #pragma unroll
            for (int d = 0; d < DI; d++) acc += sLF[l][d] * wv[d];
            sx[l][t] = fmaxf(acc, 0.0f);
        }
    }
    __syncthreads();

    // ---- GRU gates: thread t owns gate rows t (r), t+H (z), t+2H (n) ----
    float ar[LN], az[LN], an[LN], hr[LN], hz[LN], hn2[LN];
    #pragma unroll
    for (int l = 0; l < LN; l++) { ar[l]=az[l]=an[l]=hr[l]=hz[l]=hn2[l]=0.0f; }

    const float* wir = w_ih + (size_t)( t      )*HD;
    const float* wiz = w_ih + (size_t)( HD+t   )*HD;
    const float* win = w_ih + (size_t)(2*HD+t  )*HD;
    const float* whr = w_hh + (size_t)( t      )*HD;
    const float* whz = w_hh + (size_t)( HD+t   )*HD;
    const float* whn = w_hh + (size_t)(2*HD+t  )*HD;

    #pragma unroll 2
    for (int k = 0; k < HD; k++) {
        const float a0 = wir[k], a1 = wiz[k], a2 = win[k];
        const float b0 = whr[k], b1 = whz[k], b2 = whn[k];
        #pragma unroll
        for (int l = 0; l < LN; l++) {
            const float xv = sx[l][k];
            const float hv = sh[l][k];
            ar[l]  += xv*a0;  az[l]  += xv*a1;  an[l]  += xv*a2;
            hr[l]  += hv*b0;  hz[l]  += hv*b1;  hn2[l] += hv*b2;
        }
    }

    // ---- GRU elementwise ----
    const float bir = b_ih[t], biz = b_ih[HD+t], bin_ = b_ih[2*HD+t];
    const float bhr = b_hh[t], bhz = b_hh[HD+t], bhn  = b_hh[2*HD+t];
    float hnew[LN];
    #pragma unroll
    for (int l = 0; l < LN; l++) {
        const float r = sigmoidf_(ar[l]+bir + hr[l]+bhr);
        const float z = sigmoidf_(az[l]+biz + hz[l]+bhz);
        const float n = tanhf(an[l]+bin_ + r*(hn2[l]+bhn));
        hnew[l] = (1.0f - z)*n + z*sh[l][t];
    }
    __syncthreads();                 // everyone done reading old sh
    #pragma unroll
    for (int l = 0; l < LN; l++) sh[l][t] = hnew[l];
    __syncthreads();

    // ---- lane attention scores ----
    {
        const float wl = lattn_w[DI + t];
        float p[LN];
        #pragma unroll
        for (int l = 0; l < LN; l++) p[l] = wl * hnew[l];
        if (t < DI) {
            const float wd = lattn_w[t];
            #pragma unroll
            for (int l = 0; l < LN; l++) p[l] += wd * sLF[l][t];
        }
        #pragma unroll
        for (int l = 0; l < LN; l++) {
            float v = p[l];
            #pragma unroll
            for (int o = 16; o > 0; o >>= 1) v += __shfl_xor_sync(0xffffffffu, v, o);
            if (lane == 0) sred[warp*LN + l] = v;
        }
    }
    __syncthreads();
    if (t == 0) {
        float sc[LN]; float m = -3.4e38f;
        const float lb = lattn_b[0];
        #pragma unroll
        for (int l = 0; l < LN; l++) {
            sc[l] = sred[l] + sred[LN+l] + sred[2*LN+l] + sred[3*LN+l] + lb;
            m = fmaxf(m, sc[l]);
        }
        float s = 0.0f;
        #pragma unroll
        for (int l = 0; l < LN; l++) { sc[l] = expf(sc[l]-m); s += sc[l]; }
        const float inv = 1.0f/s;
        #pragma unroll
        for (int l = 0; l < LN; l++) swt[l] = sc[l]*inv;
    }
    __syncthreads();

    // ---- aggregated = sum_l w_l * h_l ----
    float agg = 0.0f;
    #pragma unroll
    for (int l = 0; l < LN; l++) agg += swt[l] * sh[l][t];
    sagg[t] = agg;
    g_agg[(size_t)bn*HD + t] = agg;
    __syncthreads();

    // ---- hg = gfc(agg) ----
    {
        float v = gfc_b[t];
        const float* gw = gfc_w + (size_t)t*HD;
        #pragma unroll 4
        for (int k = 0; k < HD; k++) v += sagg[k]*gw[k];
        shg[t] = v;
        g_hg[(size_t)bn*HD + t] = v;
    }
    __syncthreads();

    // ---- a_i (bias folded), a_j ----
    {
        const float* aw1 = ga1_w + (size_t)t*2*HD;
        float ai = ga1_b[t], aj = 0.0f;
        #pragma unroll 4
        for (int k = 0; k < HD; k++) {
            const float v = shg[k];
            ai += v*aw1[k];
            aj += v*aw1[HD+k];
        }
        g_ai[(size_t)bn*HD + t] = ai;
        g_aj[(size_t)bn*HD + t] = aj;
    }
}

// ---------------------------------------------------------------------------
// Kernel B: graph attention row + output head.  one block per (b,i)
// ---------------------------------------------------------------------------
__global__ void __launch_bounds__(128) graph_kernel(
    const float* __restrict__ adj,     // (NA, NA)
    const float* __restrict__ ga2_w,   // (HD)
    const float* __restrict__ ga2_b,   // (1)
    const float* __restrict__ gout_w,  // (HD, HD)
    const float* __restrict__ gout_b,  // (HD)
    const float* __restrict__ fc2_w,   // (NACT, 2HD)
    const float* __restrict__ fc2_b,   // (NACT)
    float* __restrict__ out)           // (BN, NACT)
{
    const int bn   = blockIdx.x;
    const int b    = bn >> 8;
    const int i    = bn & 255;
    const int t    = threadIdx.x;
    const int lane = t & 31;
    const int warp = t >> 5;

    __shared__ float sai [HD];
    __shared__ float sga2[HD];
    __shared__ float se  [NA];
    __shared__ float shp [HD];
    __shared__ float scm [HD];
    __shared__ float sag [HD];
    __shared__ float sredb[32];

    sai [t] = g_ai[(size_t)bn*HD + t];
    sga2[t] = ga2_w[t];
    __syncthreads();

    // ---- e[j] = sum_h relu(ai[h] + aj[j][h]) * ga2_w[h] + b ----
    {
        const float g2b = ga2_b[0];
        const float* ajb = g_aj + (size_t)b*NA*HD;
        for (int j = warp; j < NA; j += 4) {
            const float* ajr = ajb + (size_t)j*HD;
            float v = 0.0f;
            #pragma unroll
            for (int q = 0; q < 4; q++) {
                const int h = lane + 32*q;
                v += fmaxf(sai[h] + ajr[h], 0.0f) * sga2[h];
            }
            #pragma unroll
            for (int o = 16; o > 0; o >>= 1) v += __shfl_xor_sync(0xffffffffu, v, o);
            if (lane == 0) se[j] = v + g2b;
        }
    }
    __syncthreads();

    // ---- mask + softmax over j ----
    const float* adjr = adj + (size_t)i*NA;
    float m = -3.4e38f;
    for (int j = t; j < NA; j += 128) {
        float e = (adjr[j] == 0.0f) ? -1e9f : se[j];
        se[j] = e;
        m = fmaxf(m, e);
    }
    #pragma unroll
    for (int o = 16; o > 0; o >>= 1) m = fmaxf(m, __shfl_xor_sync(0xffffffffu, m, o));
    if (lane == 0) sredb[warp] = m;
    __syncthreads();
    m = fmaxf(fmaxf(sredb[0], sredb[1]), fmaxf(sredb[2], sredb[3]));
    __syncthreads();

    float s = 0.0f;
    for (int j = t; j < NA; j += 128) {
        const float p = expf(se[j] - m);
        se[j] = p;
        s += p;
    }
    #pragma unroll
    for (int o = 16; o > 0; o >>= 1) s += __shfl_xor_sync(0xffffffffu, s, o);
    if (lane == 0) sredb[warp] = s;
    __syncthreads();
    const float invS = 1.0f/(sredb[0] + sredb[1] + sredb[2] + sredb[3]);

    // ---- h' = (1/S) sum_j p_j * hg[b][j][:] ----
    {
        const float* hgb = g_hg + (size_t)b*NA*HD;
        float hp = 0.0f;
        #pragma unroll 8
        for (int j = 0; j < NA; j++) hp += se[j] * hgb[(size_t)j*HD + t];
        shp[t] = hp * invS;
    }
    sag[t] = g_agg[(size_t)bn*HD + t];
    __syncthreads();

    // ---- comm = gout(h') ----
    {
        float v = gout_b[t];
        const float* gw = gout_w + (size_t)t*HD;
        #pragma unroll 4
        for (int k = 0; k < HD; k++) v += shp[k]*gw[k];
        scm[t] = v;
    }
    __syncthreads();

    // ---- q = [agg, comm] @ fc2^T + b ----
    float pa[NACT];
    #pragma unroll
    for (int a = 0; a < NACT; a++)
        pa[a] = sag[t]*fc2_w[a*2*HD + t] + scm[t]*fc2_w[a*2*HD + HD + t];
    #pragma unroll
    for (int a = 0; a < NACT; a++) {
        float v = pa[a];
        #pragma unroll
        for (int o = 16; o > 0; o >>= 1) v += __shfl_xor_sync(0xffffffffu, v, o);
        if (lane == 0) sredb[a*4 + warp] = v;
    }
    __syncthreads();
    if (t < NACT) {
        const float v = sredb[t*4+0] + sredb[t*4+1] + sredb[t*4+2] + sredb[t*4+3] + fc2_b[t];
        out[(size_t)bn*NACT + t] = v;
    }
}

// ---------------------------------------------------------------------------
extern "C" void kernel_launch(void* const* d_in, const int* in_sizes, int n_in,
                              void* d_out, int out_size)
{
    const float* LF      = (const float*)d_in[0];
    const float* Hin     = (const float*)d_in[1];
    const float* adj     = (const float*)d_in[2];
    const float* fc1_w   = (const float*)d_in[3];
    const float* fc1_b   = (const float*)d_in[4];
    const float* w_ih    = (const float*)d_in[5];
    const float* w_hh    = (const float*)d_in[6];
    const float* b_ih    = (const float*)d_in[7];
    const float* b_hh    = (const float*)d_in[8];
    const float* lattn_w = (const float*)d_in[9];
    const float* lattn_b = (const float*)d_in[10];
    const float* gfc_w   = (const float*)d_in[11];
    const float* gfc_b   = (const float*)d_in[12];
    const float* ga1_w   = (const float*)d_in[13];
    const float* ga1_b   = (const float*)d_in[14];
    const float* ga2_w   = (const float*)d_in[15];
    const float* ga2_b   = (const float*)d_in[16];
    const float* gout_w  = (const float*)d_in[17];
    const float* gout_b  = (const float*)d_in[18];
    const float* fc2_w   = (const float*)d_in[19];
    const float* fc2_b   = (const float*)d_in[20];
    float* out = (float*)d_out;

    lane_kernel<<<BN, 128>>>(LF, Hin, fc1_w, fc1_b, w_ih, w_hh, b_ih, b_hh,
                             lattn_w, lattn_b, gfc_w, gfc_b, ga1_w, ga1_b);
    graph_kernel<<<BN, 128>>>(adj, ga2_w, ga2_b, gout_w, gout_b, fc2_w, fc2_b, out);
}

// round 3
// speedup vs baseline: 4.7589x; 4.7589x over previous
#include <cuda_runtime.h>
#include <math.h>

#define BSZ   8
#define NA    256
#define BN    (BSZ*NA)     // 2048
#define LN    12
#define DI    27
#define HD    128
#define NACT  8
#define KC    16           // GRU weight k-chunk
#define WPAD  18           // padded row stride for staged weights
#define AG    16           // agents per node_kernel block
#define TI    16           // i-rows per graph_kernel block

__device__ float g_agg[BN*HD];
__device__ float g_hg [BN*HD];
__device__ float g_ai [BN*HD];
__device__ float g_aj [BN*HD];

__device__ __forceinline__ float sigmoidf_(float x){ return 1.0f/(1.0f+expf(-x)); }

__device__ __forceinline__ void fma2(unsigned long long& d, unsigned long long a, unsigned long long b){
    asm("fma.rn.f32x2 %0, %1, %2, %0;" : "+l"(d) : "l"(a), "l"(b));
}
__device__ __forceinline__ float psum(unsigned long long v){
    float lo, hi; asm("mov.b64 {%0, %1}, %2;" : "=f"(lo), "=f"(hi) : "l"(v));
    return lo + hi;
}

// ---------------------------------------------------------------------------
// K1: fc1 + GRU + lane attention -> g_agg.   one block per bn, 128 threads.
// Weights staged coalesced in smem; packed f32x2 FMAs; w_hh skipped if Hin==0.
// ---------------------------------------------------------------------------
__global__ void __launch_bounds__(128) lane_kernel(
    const float* __restrict__ LF, const float* __restrict__ Hin,
    const float* __restrict__ fc1_w, const float* __restrict__ fc1_b,
    const float* __restrict__ w_ih,  const float* __restrict__ w_hh,
    const float* __restrict__ b_ih,  const float* __restrict__ b_hh,
    const float* __restrict__ lattn_w, const float* __restrict__ lattn_b)
{
    const int bn = blockIdx.x, t = threadIdx.x, lane = t & 31, warp = t >> 5;

    __shared__ __align__(16) float swbuf[3*HD*WPAD];   // 6912 f: weight stage (+fc1 alias)
    __shared__ __align__(16) float sx[LN][HD];
    __shared__ __align__(16) float sh[LN][HD];
    __shared__ float sLF[LN][DI+1];
    __shared__ float sred[4*LN];
    __shared__ float swt[LN];

    // loads
    const float* lf = LF + (size_t)bn*LN*DI;
    for (int i = t; i < LN*DI; i += 128) sLF[i/DI][i%DI] = lf[i];
    for (int i = t; i < HD*DI; i += 128) swbuf[i] = fc1_w[i];       // fc1 alias
    const float* hin = Hin + (size_t)bn*LN*HD;
    int nzl = 0;
    for (int i = t; i < LN*HD; i += 128) {
        float v = hin[i]; sh[i>>7][i&127] = v; nzl |= (v != 0.0f);
    }
    const int anynz = __syncthreads_or(nzl);

    // fc1 + relu  (smem row reads: stride 27, conflict-free)
    {
        float wv[DI];
        #pragma unroll
        for (int d = 0; d < DI; d++) wv[d] = swbuf[t*DI + d];
        const float bb = fc1_b[t];
        #pragma unroll
        for (int l = 0; l < LN; l++) {
            float a = bb;
            #pragma unroll
            for (int d = 0; d < DI; d++) a += sLF[l][d]*wv[d];
            sx[l][t] = fmaxf(a, 0.0f);
        }
    }
    __syncthreads();

    unsigned long long aR[LN], aZ[LN], aN[LN];
    #pragma unroll
    for (int l = 0; l < LN; l++) { aR[l]=0ull; aZ[l]=0ull; aN[l]=0ull; }
    float gr[LN], gz[LN], gn[LN], hr[LN], hz[LN], hn[LN];

    // ---- gi = x @ w_ih^T ----
    for (int kc = 0; kc < HD; kc += KC) {
        __syncthreads();
        for (int idx = t; idx < 3*HD*KC; idx += 128) {
            int row = idx >> 4, kk = idx & 15;
            swbuf[row*WPAD + kk] = w_ih[row*HD + kc + kk];
        }
        __syncthreads();
        #pragma unroll
        for (int kp = 0; kp < KC/2; kp++) {
            unsigned long long w0 = *(const unsigned long long*)&swbuf[(      t)*WPAD + 2*kp];
            unsigned long long w1 = *(const unsigned long long*)&swbuf[(HD  + t)*WPAD + 2*kp];
            unsigned long long w2 = *(const unsigned long long*)&swbuf[(2*HD+ t)*WPAD + 2*kp];
            #pragma unroll
            for (int l = 0; l < LN; l++) {
                unsigned long long xv = *(const unsigned long long*)&sx[l][kc + 2*kp];
                fma2(aR[l], xv, w0); fma2(aZ[l], xv, w1); fma2(aN[l], xv, w2);
            }
        }
    }
    #pragma unroll
    for (int l = 0; l < LN; l++) { gr[l]=psum(aR[l]); gz[l]=psum(aZ[l]); gn[l]=psum(aN[l]); }

    // ---- gh = h @ w_hh^T  (skipped when hidden state is all-zero) ----
    if (anynz) {
        #pragma unroll
        for (int l = 0; l < LN; l++) { aR[l]=0ull; aZ[l]=0ull; aN[l]=0ull; }
        for (int kc = 0; kc < HD; kc += KC) {
            __syncthreads();
            for (int idx = t; idx < 3*HD*KC; idx += 128) {
                int row = idx >> 4, kk = idx & 15;
                swbuf[row*WPAD + kk] = w_hh[row*HD + kc + kk];
            }
            __syncthreads();
            #pragma unroll
            for (int kp = 0; kp < KC/2; kp++) {
                unsigned long long w0 = *(const unsigned long long*)&swbuf[(      t)*WPAD + 2*kp];
                unsigned long long w1 = *(const unsigned long long*)&swbuf[(HD  + t)*WPAD + 2*kp];
                unsigned long long w2 = *(const unsigned long long*)&swbuf[(2*HD+ t)*WPAD + 2*kp];
                #pragma unroll
                for (int l = 0; l < LN; l++) {
                    unsigned long long hv = *(const unsigned long long*)&sh[l][kc + 2*kp];
                    fma2(aR[l], hv, w0); fma2(aZ[l], hv, w1); fma2(aN[l], hv, w2);
                }
            }
        }
        #pragma unroll
        for (int l = 0; l < LN; l++) { hr[l]=psum(aR[l]); hz[l]=psum(aZ[l]); hn[l]=psum(aN[l]); }
    } else {
        #pragma unroll
        for (int l = 0; l < LN; l++) { hr[l]=0.f; hz[l]=0.f; hn[l]=0.f; }
    }

    // ---- GRU elementwise ----
    const float bir=b_ih[t], biz=b_ih[HD+t], bin_=b_ih[2*HD+t];
    const float bhr=b_hh[t], bhz=b_hh[HD+t], bhn =b_hh[2*HD+t];
    float hnew[LN];
    #pragma unroll
    for (int l = 0; l < LN; l++) {
        float r = sigmoidf_(gr[l]+bir + hr[l]+bhr);
        float z = sigmoidf_(gz[l]+biz + hz[l]+bhz);
        float n = tanhf(gn[l]+bin_ + r*(hn[l]+bhn));
        hnew[l] = (1.0f - z)*n + z*sh[l][t];
    }
    __syncthreads();
    #pragma unroll
    for (int l = 0; l < LN; l++) sh[l][t] = hnew[l];
    __syncthreads();

    // ---- lane attention ----
    {
        const float wl = lattn_w[DI + t];
        float p[LN];
        #pragma unroll
        for (int l = 0; l < LN; l++) p[l] = wl*hnew[l];
        if (t < DI) {
            const float wd = lattn_w[t];
            #pragma unroll
            for (int l = 0; l < LN; l++) p[l] += wd*sLF[l][t];
        }
        #pragma unroll
        for (int l = 0; l < LN; l++) {
            float v = p[l];
            #pragma unroll
            for (int o = 16; o > 0; o >>= 1) v += __shfl_xor_sync(0xffffffffu, v, o);
            if (lane == 0) sred[warp*LN + l] = v;
        }
    }
    __syncthreads();
    if (t == 0) {
        float sc[LN]; float m = -3.4e38f;
        const float lb = lattn_b[0];
        #pragma unroll
        for (int l = 0; l < LN; l++) {
            sc[l] = sred[l] + sred[LN+l] + sred[2*LN+l] + sred[3*LN+l] + lb;
            m = fmaxf(m, sc[l]);
        }
        float s = 0.0f;
        #pragma unroll
        for (int l = 0; l < LN; l++) { sc[l] = expf(sc[l]-m); s += sc[l]; }
        const float inv = 1.0f/s;
        #pragma unroll
        for (int l = 0; l < LN; l++) swt[l] = sc[l]*inv;
    }
    __syncthreads();

    float agg = 0.0f;
    #pragma unroll
    for (int l = 0; l < LN; l++) agg += swt[l]*sh[l][t];
    g_agg[(size_t)bn*HD + t] = agg;
}

// ---------------------------------------------------------------------------
// K2: hg = gfc(agg); ai/aj = ga1 halves.  16 agents per block, 128 threads.
// Thread t = output channel; agents amortize weight reads (float4 LDG).
// ---------------------------------------------------------------------------
__global__ void __launch_bounds__(128) node_kernel(
    const float* __restrict__ gfc_w, const float* __restrict__ gfc_b,
    const float* __restrict__ ga1_w, const float* __restrict__ ga1_b)
{
    const int bn0 = blockIdx.x*AG, t = threadIdx.x;
    __shared__ __align__(16) float sa[AG][HD];
    __shared__ __align__(16) float sg[AG][HD];

    for (int idx = t; idx < AG*HD; idx += 128) sa[idx>>7][idx&127] = g_agg[(size_t)bn0*HD + idx];
    __syncthreads();

    // hg
    {
        const float4* gw = (const float4*)(gfc_w + (size_t)t*HD);
        float acc[AG];
        #pragma unroll
        for (int a = 0; a < AG; a++) acc[a] = 0.0f;
        #pragma unroll 4
        for (int k4 = 0; k4 < HD/4; k4++) {
            float4 w = gw[k4];
            #pragma unroll
            for (int a = 0; a < AG; a++) {
                float4 v = ((const float4*)sa[a])[k4];
                acc[a] += v.x*w.x + v.y*w.y + v.z*w.z + v.w*w.w;
            }
        }
        const float gb = gfc_b[t];
        #pragma unroll
        for (int a = 0; a < AG; a++) {
            float h = acc[a] + gb;
            sg[a][t] = h;
            g_hg[(size_t)(bn0 + a)*HD + t] = h;
        }
    }
    __syncthreads();

    // ai (bias folded) / aj
    {
        const float4* wa = (const float4*)(ga1_w + (size_t)t*2*HD);
        const float4* wb = (const float4*)(ga1_w + (size_t)t*2*HD + HD);
        float accA[AG], accB[AG];
        #pragma unroll
        for (int a = 0; a < AG; a++) { accA[a]=0.f; accB[a]=0.f; }
        #pragma unroll 2
        for (int k4 = 0; k4 < HD/4; k4++) {
            float4 w1 = wa[k4], w2 = wb[k4];
            #pragma unroll
            for (int a = 0; a < AG; a++) {
                float4 v = ((const float4*)sg[a])[k4];
                accA[a] += v.x*w1.x + v.y*w1.y + v.z*w1.z + v.w*w1.w;
                accB[a] += v.x*w2.x + v.y*w2.y + v.z*w2.z + v.w*w2.w;
            }
        }
        const float ab = ga1_b[t];
        #pragma unroll
        for (int a = 0; a < AG; a++) {
            g_ai[(size_t)(bn0 + a)*HD + t] = accA[a] + ab;
            g_aj[(size_t)(bn0 + a)*HD + t] = accB[a];
        }
    }
}

// ---------------------------------------------------------------------------
// K3: graph attention + head.  16 i-rows per block (grid = B*16), 128 threads.
// aj/hg streamed through smem chunks; fused softmax, h', gout, fc2.
// ---------------------------------------------------------------------------
__global__ void __launch_bounds__(128) graph_kernel(
    const float* __restrict__ adj,   const float* __restrict__ ga2_w,
    const float* __restrict__ ga2_b, const float* __restrict__ gout_w,
    const float* __restrict__ gout_b,const float* __restrict__ fc2_w,
    const float* __restrict__ fc2_b, float* __restrict__ out)
{
    const int b = blockIdx.x >> 4;
    const int i0 = (blockIdx.x & 15)*TI;
    const int t = threadIdx.x, lane = t & 31, warp = t >> 5;

    __shared__ __align__(16) float sAI[TI*HD];     // ai tile, later h' tile
    __shared__ __align__(16) float sBUF[4224];     // aj/hg chunk stage, later aggT+fc2w
    __shared__ __align__(16) float sE[TI*NA];      // e / probs, later comm (stride 132)
    __shared__ float sG2[HD];

    for (int idx = t; idx < TI*HD; idx += 128)
        sAI[idx] = g_ai[((size_t)(b*NA + i0))*HD + idx];
    sG2[t] = ga2_w[t];
    __syncthreads();

    // ---- e[i][j] ----
    const float g2b = ga2_b[0];
    const int jj = lane, iq = warp;       // warp handles i = iq, iq+4, iq+8, iq+12
    for (int jc = 0; jc < NA; jc += 32) {
        __syncthreads();
        for (int idx = t; idx < 32*HD; idx += 128) {
            int r = idx >> 7, c = idx & 127;
            sBUF[r*(HD+1) + c] = g_aj[((size_t)(b*NA + jc))*HD + idx];
        }
        __syncthreads();
        float e0=0.f, e1=0.f, e2=0.f, e3=0.f;
        const float* aj = &sBUF[jj*(HD+1)];
        #pragma unroll 4
        for (int h = 0; h < HD; h++) {
            float v = aj[h], g = sG2[h];
            e0 += fmaxf(sAI[(iq     )*HD + h] + v, 0.f)*g;
            e1 += fmaxf(sAI[(iq + 4 )*HD + h] + v, 0.f)*g;
            e2 += fmaxf(sAI[(iq + 8 )*HD + h] + v, 0.f)*g;
            e3 += fmaxf(sAI[(iq + 12)*HD + h] + v, 0.f)*g;
        }
        sE[(iq     )*NA + jc + jj] = e0 + g2b;
        sE[(iq + 4 )*NA + jc + jj] = e1 + g2b;
        sE[(iq + 8 )*NA + jc + jj] = e2 + g2b;
        sE[(iq + 12)*NA + jc + jj] = e3 + g2b;
    }
    __syncthreads();

    // ---- mask + softmax (warp per 4 rows) ----
    for (int r = 0; r < 4; r++) {
        const int i = warp*4 + r;
        const float* adjr = adj + (size_t)(i0 + i)*NA;
        float pv[8]; float m = -3.4e38f;
        #pragma unroll
        for (int q = 0; q < 8; q++) {
            int j = lane + 32*q;
            float e = sE[i*NA + j];
            if (adjr[j] == 0.0f) e = -1e9f;
            pv[q] = e; m = fmaxf(m, e);
        }
        #pragma unroll
        for (int o = 16; o > 0; o >>= 1) m = fmaxf(m, __shfl_xor_sync(0xffffffffu, m, o));
        float s = 0.0f;
        #pragma unroll
        for (int q = 0; q < 8; q++) { pv[q] = expf(pv[q]-m); s += pv[q]; }
        #pragma unroll
        for (int o = 16; o > 0; o >>= 1) s += __shfl_xor_sync(0xffffffffu, s, o);
        const float inv = 1.0f/s;
        #pragma unroll
        for (int q = 0; q < 8; q++) sE[i*NA + lane + 32*q] = pv[q]*inv;
    }
    __syncthreads();

    // ---- h' = P @ hg  (thread t = channel) ----
    float hp[TI];
    #pragma unroll
    for (int a = 0; a < TI; a++) hp[a] = 0.0f;
    for (int jc = 0; jc < NA; jc += 32) {
        __syncthreads();
        for (int idx = t; idx < 32*HD; idx += 128) {
            int r = idx >> 7, c = idx & 127;
            sBUF[r*(HD+1) + c] = g_hg[((size_t)(b*NA + jc))*HD + idx];
        }
        __syncthreads();
        for (int jr = 0; jr < 32; jr++) {
            float hv = sBUF[jr*(HD+1) + t];
            #pragma unroll
            for (int a = 0; a < TI; a++) hp[a] += sE[a*NA + jc + jr]*hv;
        }
    }
    __syncthreads();
    #pragma unroll
    for (int a = 0; a < TI; a++) sAI[a*HD + t] = hp[a];   // h' tile (ai dead)
    __syncthreads();

    // ---- comm = gout(h') -> sE region (stride 132) ----
    {
        const float4* gw = (const float4*)(gout_w + (size_t)t*HD);
        float acc[TI];
        #pragma unroll
        for (int a = 0; a < TI; a++) acc[a] = 0.0f;
        #pragma unroll 2
        for (int k4 = 0; k4 < HD/4; k4++) {
            float4 w = gw[k4];
            #pragma unroll
            for (int a = 0; a < TI; a++) {
                float4 v = ((const float4*)&sAI[a*HD])[k4];
                acc[a] += v.x*w.x + v.y*w.y + v.z*w.z + v.w*w.w;
            }
        }
        const float gb = gout_b[t];
        #pragma unroll
        for (int a = 0; a < TI; a++) sE[a*132 + t] = acc[a] + gb;
    }
    // stage agg tile (stride 132) + fc2 weights (stride 257) into sBUF
    for (int idx = t; idx < TI*HD; idx += 128) {
        int a = idx >> 7, k = idx & 127;
        sBUF[a*132 + k] = g_agg[((size_t)(b*NA + i0))*HD + idx];
    }
    for (int idx = t; idx < NACT*2*HD; idx += 128) {
        int act = idx >> 8, k = idx & 255;
        sBUF[TI*132 + act*257 + k] = fc2_w[idx];
    }
    __syncthreads();

    // ---- q = [agg, comm] @ fc2^T + b ----
    {
        const int a = t >> 3, act = t & 7;
        float acc = fc2_b[act];
        const float* sagg = &sBUF[a*132];
        const float* sw1  = &sBUF[TI*132 + act*257];
        const float* scm  = &sE[a*132];
        #pragma unroll 4
        for (int k = 0; k < HD; k++) acc += sagg[k]*sw1[k];
        #pragma unroll 4
        for (int k = 0; k < HD; k++) acc += scm[k]*sw1[HD + k];
        out[((size_t)(b*NA + i0 + a))*NACT + act] = acc;
    }
}

// ---------------------------------------------------------------------------
extern "C" void kernel_launch(void* const* d_in, const int* in_sizes, int n_in,
                              void* d_out, int out_size)
{
    const float* LF      = (const float*)d_in[0];
    const float* Hin     = (const float*)d_in[1];
    const float* adj     = (const float*)d_in[2];
    const float* fc1_w   = (const float*)d_in[3];
    const float* fc1_b   = (const float*)d_in[4];
    const float* w_ih    = (const float*)d_in[5];
    const float* w_hh    = (const float*)d_in[6];
    const float* b_ih    = (const float*)d_in[7];
    const float* b_hh    = (const float*)d_in[8];
    const float* lattn_w = (const float*)d_in[9];
    const float* lattn_b = (const float*)d_in[10];
    const float* gfc_w   = (const float*)d_in[11];
    const float* gfc_b   = (const float*)d_in[12];
    const float* ga1_w   = (const float*)d_in[13];
    const float* ga1_b   = (const float*)d_in[14];
    const float* ga2_w   = (const float*)d_in[15];
    const float* ga2_b   = (const float*)d_in[16];
    const float* gout_w  = (const float*)d_in[17];
    const float* gout_b  = (const float*)d_in[18];
    const float* fc2_w   = (const float*)d_in[19];
    const float* fc2_b   = (const float*)d_in[20];
    float* out = (float*)d_out;

    lane_kernel<<<BN, 128>>>(LF, Hin, fc1_w, fc1_b, w_ih, w_hh, b_ih, b_hh,
                             lattn_w, lattn_b);
    node_kernel<<<BN/AG, 128>>>(gfc_w, gfc_b, ga1_w, ga1_b);
    graph_kernel<<<BSZ*(NA/TI), 128>>>(adj, ga2_w, ga2_b, gout_w, gout_b,
                                       fc2_w, fc2_b, out);
}

// round 4
// speedup vs baseline: 5.7805x; 1.2147x over previous
#include <cuda_runtime.h>
#include <math.h>

#define BSZ   8
#define NA    256
#define BN    (BSZ*NA)     // 2048
#define LN    12
#define DI    27
#define HD    128
#define NACT  8
#define AG    16           // agents per node_kernel block
#define TI    16           // i-rows per graph_kernel block

#define RPAD  385          // float2 row stride of transposed weight tile
#define LGRID 148          // persistent lane blocks

// smem float offsets for lane_kernel
#define OFF_W2   0                       // 64*385 float2 = 49280 floats
#define OFF_FC1  49280                   // 128*27 = 3456
#define OFF_SX   52736                   // 12*128
#define OFF_SH   54272                   // 12*128
#define OFF_SLF  55808                   // 12*28
#define OFF_SRED 56144                   // 8*6
#define OFF_SWT  56192                   // 12
#define SMEM_FLOATS 56208
#define SMEM_BYTES  (SMEM_FLOATS*4)

__device__ float g_agg[BN*HD];
__device__ float g_hg [BN*HD];
__device__ float g_ai [BN*HD];
__device__ float g_aj [BN*HD];

__device__ __forceinline__ float sigmoidf_(float x){ return 1.0f/(1.0f+expf(-x)); }
typedef unsigned long long u64;
__device__ __forceinline__ void fma2(u64& d, u64 a, u64 b){
    asm("fma.rn.f32x2 %0, %1, %2, %0;" : "+l"(d) : "l"(a), "l"(b));
}
__device__ __forceinline__ float psum(u64 v){
    float lo, hi; asm("mov.b64 {%0, %1}, %2;" : "=f"(lo), "=f"(hi) : "l"(v));
    return lo + hi;
}

// ---------------------------------------------------------------------------
// K1 (persistent): fc1 + GRU + lane attention -> g_agg
// 148 blocks x 256 threads. w_ih staged transposed in smem ONCE per block,
// then grid-stride over agents. Thread (c=t&127, lh=t>>7) owns gate rows
// c, c+128, c+256 for lanes lh*6..lh*6+5 (18 f32x2 accumulators).
// ---------------------------------------------------------------------------
__global__ void __launch_bounds__(256) lane_kernel(
    const float* __restrict__ LF, const float* __restrict__ Hin,
    const float* __restrict__ fc1_w, const float* __restrict__ fc1_b,
    const float* __restrict__ w_ih,  const float* __restrict__ w_hh,
    const float* __restrict__ b_ih,  const float* __restrict__ b_hh,
    const float* __restrict__ lattn_w, const float* __restrict__ lattn_b)
{
    extern __shared__ __align__(16) float smem[];
    float2* sW2  = (float2*)&smem[OFF_W2];
    float*  sFC1 = &smem[OFF_FC1];
    float*  sX   = &smem[OFF_SX];
    float*  sH   = &smem[OFF_SH];
    float*  sLFm = &smem[OFF_SLF];
    float*  sRED = &smem[OFF_SRED];
    float*  sWT  = &smem[OFF_SWT];

    const int t    = threadIdx.x;
    const int lane = t & 31, warp = t >> 5;
    const int c    = t & 127;            // channel / base gate row
    const int lh   = t >> 7;             // lane-half (0: lanes 0-5, 1: lanes 6-11)

    // ---- one-time staging: w_ih transposed (k-pair major), fc1 weights ----
    {
        const float2* wg = (const float2*)w_ih;       // [384][64] float2
        for (int i = t; i < 384*64; i += 256) {
            int row = i >> 6, kp = i & 63;
            sW2[kp*RPAD + row] = wg[i];
        }
        for (int i = t; i < HD*DI; i += 256) sFC1[i] = fc1_w[i];
    }
    // per-thread constants
    float wv[DI];
    const float fb = fc1_b[c];
    const float bir = b_ih[c], biz = b_ih[HD+c], bin_ = b_ih[2*HD+c];
    const float bhr = b_hh[c], bhz = b_hh[HD+c], bhn  = b_hh[2*HD+c];
    const float wl  = lattn_w[DI + c];
    const float wd  = (c < DI) ? lattn_w[c] : 0.0f;
    const float lb  = lattn_b[0];
    __syncthreads();
    #pragma unroll
    for (int d = 0; d < DI; d++) wv[d] = sFC1[c*DI + d];

    // ---- agent loop ----
    for (int a = blockIdx.x; a < BN; a += LGRID) {
        __syncthreads();   // previous iteration readers done

        // load LF + hidden
        const float* lf = LF + (size_t)a*LN*DI;
        for (int i = t; i < LN*DI; i += 256) sLFm[(i/DI)*28 + (i%DI)] = lf[i];
        const float* hin = Hin + (size_t)a*LN*HD;
        int nzl = 0;
        for (int i = t; i < LN*HD; i += 256) {
            float v = hin[i]; sH[i] = v; nzl |= (v != 0.0f);
        }
        const int anynz = __syncthreads_or(nzl);

        // fc1 + relu : x[l][c]
        #pragma unroll
        for (int l = 0; l < 6; l++) {
            const int l6 = lh*6 + l;
            float acc = fb;
            #pragma unroll
            for (int d = 0; d < DI; d++) acc += sLFm[l6*28 + d]*wv[d];
            sX[l6*HD + c] = fmaxf(acc, 0.0f);
        }
        __syncthreads();

        // gi = x @ w_ih^T : 18 packed accumulators
        u64 aR[6], aZ[6], aN[6];
        #pragma unroll
        for (int l = 0; l < 6; l++) { aR[l]=0ull; aZ[l]=0ull; aN[l]=0ull; }
        #pragma unroll 2
        for (int kp = 0; kp < 64; kp++) {
            const u64 w0 = *(const u64*)&sW2[kp*RPAD + c      ];
            const u64 w1 = *(const u64*)&sW2[kp*RPAD + c + 128];
            const u64 w2 = *(const u64*)&sW2[kp*RPAD + c + 256];
            #pragma unroll
            for (int l = 0; l < 6; l++) {
                const u64 xv = *(const u64*)&sX[(lh*6 + l)*HD + 2*kp];
                fma2(aR[l], xv, w0); fma2(aZ[l], xv, w1); fma2(aN[l], xv, w2);
            }
        }

        // gh fallback (hidden state nonzero) — direct gmem reads, correct but slow
        float hR[6], hZ[6], hN[6];
        #pragma unroll
        for (int l = 0; l < 6; l++) { hR[l]=0.f; hZ[l]=0.f; hN[l]=0.f; }
        if (anynz) {
            for (int k = 0; k < HD; k++) {
                const float q0 = w_hh[(size_t)(c      )*HD + k];
                const float q1 = w_hh[(size_t)(c + 128)*HD + k];
                const float q2 = w_hh[(size_t)(c + 256)*HD + k];
                #pragma unroll
                for (int l = 0; l < 6; l++) {
                    const float hv = sH[(lh*6 + l)*HD + k];
                    hR[l] += hv*q0; hZ[l] += hv*q1; hN[l] += hv*q2;
                }
            }
        }

        // GRU elementwise
        float hnew[6];
        #pragma unroll
        for (int l = 0; l < 6; l++) {
            const float r = sigmoidf_(psum(aR[l]) + bir + hR[l] + bhr);
            const float z = sigmoidf_(psum(aZ[l]) + biz + hZ[l] + bhz);
            const float n = tanhf(psum(aN[l]) + bin_ + r*(hN[l] + bhn));
            hnew[l] = (1.0f - z)*n + z*sH[(lh*6 + l)*HD + c];
        }
        __syncthreads();
        #pragma unroll
        for (int l = 0; l < 6; l++) sH[(lh*6 + l)*HD + c] = hnew[l];

        // lane attention scores: per-(lane,channel) partials -> warp reduce
        #pragma unroll
        for (int l = 0; l < 6; l++) {
            float v = wl*hnew[l];
            if (c < DI) v += wd*sLFm[(lh*6 + l)*28 + c];
            #pragma unroll
            for (int o = 16; o > 0; o >>= 1) v += __shfl_xor_sync(0xffffffffu, v, o);
            if (lane == 0) sRED[warp*6 + l] = v;
        }
        __syncthreads();
        if (t == 0) {
            float sc[LN]; float m = -3.4e38f;
            #pragma unroll
            for (int l = 0; l < LN; l++) {
                const int wbase = (l < 6) ? 0 : 4;
                const int lr = (l < 6) ? l : l - 6;
                sc[l] = sRED[(wbase  )*6 + lr] + sRED[(wbase+1)*6 + lr]
                      + sRED[(wbase+2)*6 + lr] + sRED[(wbase+3)*6 + lr] + lb;
                m = fmaxf(m, sc[l]);
            }
            float s = 0.0f;
            #pragma unroll
            for (int l = 0; l < LN; l++) { sc[l] = expf(sc[l]-m); s += sc[l]; }
            const float inv = 1.0f/s;
            #pragma unroll
            for (int l = 0; l < LN; l++) sWT[l] = sc[l]*inv;
        }
        __syncthreads();

        // aggregated
        if (lh == 0) {
            float agg = 0.0f;
            #pragma unroll
            for (int l = 0; l < LN; l++) agg += sWT[l]*sH[l*HD + c];
            g_agg[(size_t)a*HD + c] = agg;
        }
    }
}

// ---------------------------------------------------------------------------
// K2: hg = gfc(agg); ai/aj = ga1 halves.  16 agents per block, 128 threads.
// ---------------------------------------------------------------------------
__global__ void __launch_bounds__(128) node_kernel(
    const float* __restrict__ gfc_w, const float* __restrict__ gfc_b,
    const float* __restrict__ ga1_w, const float* __restrict__ ga1_b)
{
    const int bn0 = blockIdx.x*AG, t = threadIdx.x;
    __shared__ __align__(16) float sa[AG][HD];
    __shared__ __align__(16) float sg[AG][HD];

    for (int idx = t; idx < AG*HD; idx += 128) sa[idx>>7][idx&127] = g_agg[(size_t)bn0*HD + idx];
    __syncthreads();

    {
        const float4* gw = (const float4*)(gfc_w + (size_t)t*HD);
        float acc[AG];
        #pragma unroll
        for (int a = 0; a < AG; a++) acc[a] = 0.0f;
        #pragma unroll 4
        for (int k4 = 0; k4 < HD/4; k4++) {
            float4 w = gw[k4];
            #pragma unroll
            for (int a = 0; a < AG; a++) {
                float4 v = ((const float4*)sa[a])[k4];
                acc[a] += v.x*w.x + v.y*w.y + v.z*w.z + v.w*w.w;
            }
        }
        const float gb = gfc_b[t];
        #pragma unroll
        for (int a = 0; a < AG; a++) {
            float h = acc[a] + gb;
            sg[a][t] = h;
            g_hg[(size_t)(bn0 + a)*HD + t] = h;
        }
    }
    __syncthreads();

    {
        const float4* wa = (const float4*)(ga1_w + (size_t)t*2*HD);
        const float4* wb = (const float4*)(ga1_w + (size_t)t*2*HD + HD);
        float accA[AG], accB[AG];
        #pragma unroll
        for (int a = 0; a < AG; a++) { accA[a]=0.f; accB[a]=0.f; }
        #pragma unroll 2
        for (int k4 = 0; k4 < HD/4; k4++) {
            float4 w1 = wa[k4], w2 = wb[k4];
            #pragma unroll
            for (int a = 0; a < AG; a++) {
                float4 v = ((const float4*)sg[a])[k4];
                accA[a] += v.x*w1.x + v.y*w1.y + v.z*w1.z + v.w*w1.w;
                accB[a] += v.x*w2.x + v.y*w2.y + v.z*w2.z + v.w*w2.w;
            }
        }
        const float ab = ga1_b[t];
        #pragma unroll
        for (int a = 0; a < AG; a++) {
            g_ai[(size_t)(bn0 + a)*HD + t] = accA[a] + ab;
            g_aj[(size_t)(bn0 + a)*HD + t] = accB[a];
        }
    }
}

// ---------------------------------------------------------------------------
// K3: graph attention + head.  16 i-rows per block, 128 threads.
// ---------------------------------------------------------------------------
__global__ void __launch_bounds__(128) graph_kernel(
    const float* __restrict__ adj,   const float* __restrict__ ga2_w,
    const float* __restrict__ ga2_b, const float* __restrict__ gout_w,
    const float* __restrict__ gout_b,const float* __restrict__ fc2_w,
    const float* __restrict__ fc2_b, float* __restrict__ out)
{
    const int b = blockIdx.x >> 4;
    const int i0 = (blockIdx.x & 15)*TI;
    const int t = threadIdx.x, lane = t & 31, warp = t >> 5;

    __shared__ __align__(16) float sAI[TI*HD];
    __shared__ __align__(16) float sBUF[4224];
    __shared__ __align__(16) float sE[TI*NA];
    __shared__ float sG2[HD];

    for (int idx = t; idx < TI*HD; idx += 128)
        sAI[idx] = g_ai[((size_t)(b*NA + i0))*HD + idx];
    sG2[t] = ga2_w[t];
    __syncthreads();

    const float g2b = ga2_b[0];
    const int jj = lane, iq = warp;
    for (int jc = 0; jc < NA; jc += 32) {
        __syncthreads();
        for (int idx = t; idx < 32*HD; idx += 128) {
            int r = idx >> 7, cc = idx & 127;
            sBUF[r*(HD+1) + cc] = g_aj[((size_t)(b*NA + jc))*HD + idx];
        }
        __syncthreads();
        float e0=0.f, e1=0.f, e2=0.f, e3=0.f;
        const float* aj = &sBUF[jj*(HD+1)];
        #pragma unroll 4
        for (int h = 0; h < HD; h++) {
            float v = aj[h], g = sG2[h];
            e0 += fmaxf(sAI[(iq     )*HD + h] + v, 0.f)*g;
            e1 += fmaxf(sAI[(iq + 4 )*HD + h] + v, 0.f)*g;
            e2 += fmaxf(sAI[(iq + 8 )*HD + h] + v, 0.f)*g;
            e3 += fmaxf(sAI[(iq + 12)*HD + h] + v, 0.f)*g;
        }
        sE[(iq     )*NA + jc + jj] = e0 + g2b;
        sE[(iq + 4 )*NA + jc + jj] = e1 + g2b;
        sE[(iq + 8 )*NA + jc + jj] = e2 + g2b;
        sE[(iq + 12)*NA + jc + jj] = e3 + g2b;
    }
    __syncthreads();

    for (int r = 0; r < 4; r++) {
        const int i = warp*4 + r;
        const float* adjr = adj + (size_t)(i0 + i)*NA;
        float pv[8]; float m = -3.4e38f;
        #pragma unroll
        for (int q = 0; q < 8; q++) {
            int j = lane + 32*q;
            float e = sE[i*NA + j];
            if (adjr[j] == 0.0f) e = -1e9f;
            pv[q] = e; m = fmaxf(m, e);
        }
        #pragma unroll
        for (int o = 16; o > 0; o >>= 1) m = fmaxf(m, __shfl_xor_sync(0xffffffffu, m, o));
        float s = 0.0f;
        #pragma unroll
        for (int q = 0; q < 8; q++) { pv[q] = expf(pv[q]-m); s += pv[q]; }
        #pragma unroll
        for (int o = 16; o > 0; o >>= 1) s += __shfl_xor_sync(0xffffffffu, s, o);
        const float inv = 1.0f/s;
        #pragma unroll
        for (int q = 0; q < 8; q++) sE[i*NA + lane + 32*q] = pv[q]*inv;
    }
    __syncthreads();

    float hp[TI];
    #pragma unroll
    for (int a = 0; a < TI; a++) hp[a] = 0.0f;
    for (int jc = 0; jc < NA; jc += 32) {
        __syncthreads();
        for (int idx = t; idx < 32*HD; idx += 128) {
            int r = idx >> 7, cc = idx & 127;
            sBUF[r*(HD+1) + cc] = g_hg[((size_t)(b*NA + jc))*HD + idx];
        }
        __syncthreads();
        for (int jr = 0; jr < 32; jr++) {
            float hv = sBUF[jr*(HD+1) + t];
            #pragma unroll
            for (int a = 0; a < TI; a++) hp[a] += sE[a*NA + jc + jr]*hv;
        }
    }
    __syncthreads();
    #pragma unroll
    for (int a = 0; a < TI; a++) sAI[a*HD + t] = hp[a];
    __syncthreads();

    {
        const float4* gw = (const float4*)(gout_w + (size_t)t*HD);
        float acc[TI];
        #pragma unroll
        for (int a = 0; a < TI; a++) acc[a] = 0.0f;
        #pragma unroll 2
        for (int k4 = 0; k4 < HD/4; k4++) {
            float4 w = gw[k4];
            #pragma unroll
            for (int a = 0; a < TI; a++) {
                float4 v = ((const float4*)&sAI[a*HD])[k4];
                acc[a] += v.x*w.x + v.y*w.y + v.z*w.z + v.w*w.w;
            }
        }
        const float gb = gout_b[t];
        #pragma unroll
        for (int a = 0; a < TI; a++) sE[a*132 + t] = acc[a] + gb;
    }
    for (int idx = t; idx < TI*HD; idx += 128) {
        int a = idx >> 7, k = idx & 127;
        sBUF[a*132 + k] = g_agg[((size_t)(b*NA + i0))*HD + idx];
    }
    for (int idx = t; idx < NACT*2*HD; idx += 128) {
        int act = idx >> 8, k = idx & 255;
        sBUF[TI*132 + act*257 + k] = fc2_w[idx];
    }
    __syncthreads();

    {
        const int a = t >> 3, act = t & 7;
        float acc = fc2_b[act];
        const float* sagg = &sBUF[a*132];
        const float* sw1  = &sBUF[TI*132 + act*257];
        const float* scm  = &sE[a*132];
        #pragma unroll 4
        for (int k = 0; k < HD; k++) acc += sagg[k]*sw1[k];
        #pragma unroll 4
        for (int k = 0; k < HD; k++) acc += scm[k]*sw1[HD + k];
        out[((size_t)(b*NA + i0 + a))*NACT + act] = acc;
    }
}

// ---------------------------------------------------------------------------
extern "C" void kernel_launch(void* const* d_in, const int* in_sizes, int n_in,
                              void* d_out, int out_size)
{
    const float* LF      = (const float*)d_in[0];
    const float* Hin     = (const float*)d_in[1];
    const float* adj     = (const float*)d_in[2];
    const float* fc1_w   = (const float*)d_in[3];
    const float* fc1_b   = (const float*)d_in[4];
    const float* w_ih    = (const float*)d_in[5];
    const float* w_hh    = (const float*)d_in[6];
    const float* b_ih    = (const float*)d_in[7];
    const float* b_hh    = (const float*)d_in[8];
    const float* lattn_w = (const float*)d_in[9];
    const float* lattn_b = (const float*)d_in[10];
    const float* gfc_w   = (const float*)d_in[11];
    const float* gfc_b   = (const float*)d_in[12];
    const float* ga1_w   = (const float*)d_in[13];
    const float* ga1_b   = (const float*)d_in[14];
    const float* ga2_w   = (const float*)d_in[15];
    const float* ga2_b   = (const float*)d_in[16];
    const float* gout_w  = (const float*)d_in[17];
    const float* gout_b  = (const float*)d_in[18];
    const float* fc2_w   = (const float*)d_in[19];
    const float* fc2_b   = (const float*)d_in[20];
    float* out = (float*)d_out;

    static int smem_set = 0;
    if (!smem_set) {
        cudaFuncSetAttribute(lane_kernel, cudaFuncAttributeMaxDynamicSharedMemorySize, SMEM_BYTES);
        smem_set = 1;
    }

    lane_kernel<<<LGRID, 256, SMEM_BYTES>>>(LF, Hin, fc1_w, fc1_b, w_ih, w_hh,
                                            b_ih, b_hh, lattn_w, lattn_b);
    node_kernel<<<BN/AG, 128>>>(gfc_w, gfc_b, ga1_w, ga1_b);
    graph_kernel<<<BSZ*(NA/TI), 128>>>(adj, ga2_w, ga2_b, gout_w, gout_b,
                                       fc2_w, fc2_b, out);
}

// round 5
// speedup vs baseline: 6.7875x; 1.1742x over previous
#include <cuda_runtime.h>
#include <math.h>

#define BSZ   8
#define NA    256
#define BN    (BSZ*NA)     // 2048
#define LN    12
#define DI    27
#define HD    128
#define NACT  8
#define AG    16           // agents per node_kernel block
#define TI    16           // i-rows per graph_kernel block

#define RPAD4 385          // float4 row stride of transposed weight tile
#define LGRID 148          // persistent lane blocks

// smem float offsets for lane_kernel
#define OFF_W4   0                       // 32*385 float4 = 49280 floats
#define OFF_FC1  49280                   // 128*27 = 3456
#define OFF_SX   52736                   // 12*128
#define OFF_SH   54272                   // 12*128
#define OFF_SLF  55808                   // 12*28
#define OFF_SRED 56144                   // 8*6
#define OFF_SWT  56192                   // 12
#define SMEM_FLOATS 56208
#define SMEM_BYTES  (SMEM_FLOATS*4)

__device__ float g_agg[BN*HD];
__device__ float g_hg [BN*HD];
__device__ float g_ai [BN*HD];
__device__ float g_aj [BN*HD];

__device__ __forceinline__ float sigmoidf_(float x){ return 1.0f/(1.0f+expf(-x)); }
typedef unsigned long long u64;
__device__ __forceinline__ void fma2(u64& d, u64 a, u64 b){
    asm("fma.rn.f32x2 %0, %1, %2, %0;" : "+l"(d) : "l"(a), "l"(b));
}
__device__ __forceinline__ float psum(u64 v){
    float lo, hi; asm("mov.b64 {%0, %1}, %2;" : "=f"(lo), "=f"(hi) : "l"(v));
    return lo + hi;
}

// ---------------------------------------------------------------------------
// K1 (persistent, pipelined): fc1 + GRU + lane attention -> g_agg
// 148 blocks x 256 threads. w_ih staged transposed (float4 rows) once.
// Thread (c=t&127, lh=t>>7) owns gate rows c,c+128,c+256 for 6 lanes.
// Next agent's LF/Hin prefetched into registers during current compute.
// ---------------------------------------------------------------------------
__global__ void __launch_bounds__(256) lane_kernel(
    const float* __restrict__ LF, const float* __restrict__ Hin,
    const float* __restrict__ fc1_w, const float* __restrict__ fc1_b,
    const float* __restrict__ w_ih,  const float* __restrict__ w_hh,
    const float* __restrict__ b_ih,  const float* __restrict__ b_hh,
    const float* __restrict__ lattn_w, const float* __restrict__ lattn_b)
{
    extern __shared__ __align__(16) float smem[];
    float4* sW4  = (float4*)&smem[OFF_W4];
    float*  sFC1 = &smem[OFF_FC1];
    float*  sX   = &smem[OFF_SX];
    float*  sH   = &smem[OFF_SH];
    float*  sLFm = &smem[OFF_SLF];
    float*  sRED = &smem[OFF_SRED];
    float*  sWT  = &smem[OFF_SWT];

    const int t    = threadIdx.x;
    const int lane = t & 31, warp = t >> 5;
    const int c    = t & 127;            // channel / base gate row
    const int lh   = t >> 7;             // lane-half

    // ---- one-time staging: w_ih transposed (kp2-major float4), fc1 ----
    {
        const float4* wg = (const float4*)w_ih;       // [384][32] float4
        for (int i = t; i < 384*32; i += 256) {
            int row = i >> 5, kp2 = i & 31;
            sW4[kp2*RPAD4 + row] = wg[i];
        }
        for (int i = t; i < HD*DI; i += 256) sFC1[i] = fc1_w[i];
    }
    // per-thread constants
    float wv[DI];
    const float fb = fc1_b[c];
    const float bir = b_ih[c], biz = b_ih[HD+c], bin_ = b_ih[2*HD+c];
    const float bhr = b_hh[c], bhz = b_hh[HD+c], bhn  = b_hh[2*HD+c];
    const float wl  = lattn_w[DI + c];
    const float wd  = (c < DI) ? lattn_w[c] : 0.0f;
    const float lb  = lattn_b[0];
    // precomputed LF scatter targets (t -> padded smem offset)
    const int lfv0 = (t < LN*DI);
    const int lfv1 = (t + 256 < LN*DI);
    const int lfo0 = (t/DI)*28 + (t%DI);
    const int lfo1 = ((t+256)/DI)*28 + ((t+256)%DI);
    __syncthreads();
    #pragma unroll
    for (int d = 0; d < DI; d++) wv[d] = sFC1[c*DI + d];

    // ---- prefetch first agent ----
    float pLF0 = 0.f, pLF1 = 0.f, pH[6];
    {
        const int a0 = blockIdx.x;
        const float* lf  = LF  + (size_t)a0*LN*DI;
        if (lfv0) pLF0 = lf[t];
        if (lfv1) pLF1 = lf[t+256];
        const float* hin = Hin + (size_t)a0*LN*HD;
        #pragma unroll
        for (int j = 0; j < 6; j++) pH[j] = hin[t + 256*j];
    }

    // ---- agent loop ----
    for (int a = blockIdx.x; a < BN; a += LGRID) {
        __syncthreads();   // previous iteration readers done

        // commit prefetched regs to smem + nz flag
        if (lfv0) sLFm[lfo0] = pLF0;
        if (lfv1) sLFm[lfo1] = pLF1;
        int nzl = 0;
        #pragma unroll
        for (int j = 0; j < 6; j++) { sH[t + 256*j] = pH[j]; nzl |= (pH[j] != 0.0f); }
        const int anynz = __syncthreads_or(nzl);

        // prefetch next agent (overlaps with the GEMM below)
        const int an = a + LGRID;
        if (an < BN) {
            const float* lf  = LF  + (size_t)an*LN*DI;
            if (lfv0) pLF0 = lf[t];
            if (lfv1) pLF1 = lf[t+256];
            const float* hin = Hin + (size_t)an*LN*HD;
            #pragma unroll
            for (int j = 0; j < 6; j++) pH[j] = hin[t + 256*j];
        }

        // fc1 + relu : x[l][c]
        #pragma unroll
        for (int l = 0; l < 6; l++) {
            const int l6 = lh*6 + l;
            float acc = fb;
            #pragma unroll
            for (int d = 0; d < DI; d++) acc += sLFm[l6*28 + d]*wv[d];
            sX[l6*HD + c] = fmaxf(acc, 0.0f);
        }
        __syncthreads();

        // gi = x @ w_ih^T : 18 packed accumulators, LDS.128 operands
        u64 aR[6], aZ[6], aN[6];
        #pragma unroll
        for (int l = 0; l < 6; l++) { aR[l]=0ull; aZ[l]=0ull; aN[l]=0ull; }
        {
            const float4* w0p = sW4 + c;
            const float4* w1p = sW4 + c + 128;
            const float4* w2p = sW4 + c + 256;
            #pragma unroll 2
            for (int kp2 = 0; kp2 < 32; kp2++) {
                const ulonglong2 w0 = *(const ulonglong2*)(w0p + kp2*RPAD4);
                const ulonglong2 w1 = *(const ulonglong2*)(w1p + kp2*RPAD4);
                const ulonglong2 w2 = *(const ulonglong2*)(w2p + kp2*RPAD4);
                #pragma unroll
                for (int l = 0; l < 6; l++) {
                    const ulonglong2 xv = *(const ulonglong2*)&sX[(lh*6 + l)*HD + kp2*4];
                    fma2(aR[l], xv.x, w0.x); fma2(aR[l], xv.y, w0.y);
                    fma2(aZ[l], xv.x, w1.x); fma2(aZ[l], xv.y, w1.y);
                    fma2(aN[l], xv.x, w2.x); fma2(aN[l], xv.y, w2.y);
                }
            }
        }

        // gh fallback (hidden state nonzero) — direct gmem reads, rare path
        float hR[6], hZ[6], hN[6];
        #pragma unroll
        for (int l = 0; l < 6; l++) { hR[l]=0.f; hZ[l]=0.f; hN[l]=0.f; }
        if (anynz) {
            for (int k = 0; k < HD; k++) {
                const float q0 = w_hh[(size_t)(c      )*HD + k];
                const float q1 = w_hh[(size_t)(c + 128)*HD + k];
                const float q2 = w_hh[(size_t)(c + 256)*HD + k];
                #pragma unroll
                for (int l = 0; l < 6; l++) {
                    const float hv = sH[(lh*6 + l)*HD + k];
                    hR[l] += hv*q0; hZ[l] += hv*q1; hN[l] += hv*q2;
                }
            }
        }

        // GRU elementwise
        float hnew[6];
        #pragma unroll
        for (int l = 0; l < 6; l++) {
            const float r = sigmoidf_(psum(aR[l]) + bir + hR[l] + bhr);
            const float z = sigmoidf_(psum(aZ[l]) + biz + hZ[l] + bhz);
            const float n = tanhf(psum(aN[l]) + bin_ + r*(hN[l] + bhn));
            hnew[l] = (1.0f - z)*n + z*sH[(lh*6 + l)*HD + c];
        }
        __syncthreads();          // all gi/gh reads of sX/sH complete
        #pragma unroll
        for (int l = 0; l < 6; l++) sX[(lh*6 + l)*HD + c] = hnew[l];  // h -> sX

        // lane attention scores
        #pragma unroll
        for (int l = 0; l < 6; l++) {
            float v = wl*hnew[l];
            if (c < DI) v += wd*sLFm[(lh*6 + l)*28 + c];
            #pragma unroll
            for (int o = 16; o > 0; o >>= 1) v += __shfl_xor_sync(0xffffffffu, v, o);
            if (lane == 0) sRED[warp*6 + l] = v;
        }
        __syncthreads();
        if (t == 0) {
            float sc[LN]; float m = -3.4e38f;
            #pragma unroll
            for (int l = 0; l < LN; l++) {
                const int wbase = (l < 6) ? 0 : 4;
                const int lr = (l < 6) ? l : l - 6;
                sc[l] = sRED[(wbase  )*6 + lr] + sRED[(wbase+1)*6 + lr]
                      + sRED[(wbase+2)*6 + lr] + sRED[(wbase+3)*6 + lr] + lb;
                m = fmaxf(m, sc[l]);
            }
            float s = 0.0f;
            #pragma unroll
            for (int l = 0; l < LN; l++) { sc[l] = expf(sc[l]-m); s += sc[l]; }
            const float inv = 1.0f/s;
            #pragma unroll
            for (int l = 0; l < LN; l++) sWT[l] = sc[l]*inv;
        }
        __syncthreads();

        // aggregated (h lives in sX)
        if (lh == 0) {
            float agg = 0.0f;
            #pragma unroll
            for (int l = 0; l < LN; l++) agg += sWT[l]*sX[l*HD + c];
            g_agg[(size_t)a*HD + c] = agg;
        }
    }
}

// ---------------------------------------------------------------------------
// K2: hg = gfc(agg); ai/aj = ga1 halves.  16 agents per block, 128 threads.
// ---------------------------------------------------------------------------
__global__ void __launch_bounds__(128) node_kernel(
    const float* __restrict__ gfc_w, const float* __restrict__ gfc_b,
    const float* __restrict__ ga1_w, const float* __restrict__ ga1_b)
{
    const int bn0 = blockIdx.x*AG, t = threadIdx.x;
    __shared__ __align__(16) float sa[AG][HD];
    __shared__ __align__(16) float sg[AG][HD];

    for (int idx = t; idx < AG*HD; idx += 128) sa[idx>>7][idx&127] = g_agg[(size_t)bn0*HD + idx];
    __syncthreads();

    {
        const float4* gw = (const float4*)(gfc_w + (size_t)t*HD);
        float acc[AG];
        #pragma unroll
        for (int a = 0; a < AG; a++) acc[a] = 0.0f;
        #pragma unroll 4
        for (int k4 = 0; k4 < HD/4; k4++) {
            float4 w = gw[k4];
            #pragma unroll
            for (int a = 0; a < AG; a++) {
                float4 v = ((const float4*)sa[a])[k4];
                acc[a] += v.x*w.x + v.y*w.y + v.z*w.z + v.w*w.w;
            }
        }
        const float gb = gfc_b[t];
        #pragma unroll
        for (int a = 0; a < AG; a++) {
            float h = acc[a] + gb;
            sg[a][t] = h;
            g_hg[(size_t)(bn0 + a)*HD + t] = h;
        }
    }
    __syncthreads();

    {
        const float4* wa = (const float4*)(ga1_w + (size_t)t*2*HD);
        const float4* wb = (const float4*)(ga1_w + (size_t)t*2*HD + HD);
        float accA[AG], accB[AG];
        #pragma unroll
        for (int a = 0; a < AG; a++) { accA[a]=0.f; accB[a]=0.f; }
        #pragma unroll 2
        for (int k4 = 0; k4 < HD/4; k4++) {
            float4 w1 = wa[k4], w2 = wb[k4];
            #pragma unroll
            for (int a = 0; a < AG; a++) {
                float4 v = ((const float4*)sg[a])[k4];
                accA[a] += v.x*w1.x + v.y*w1.y + v.z*w1.z + v.w*w1.w;
                accB[a] += v.x*w2.x + v.y*w2.y + v.z*w2.z + v.w*w2.w;
            }
        }
        const float ab = ga1_b[t];
        #pragma unroll
        for (int a = 0; a < AG; a++) {
            g_ai[(size_t)(bn0 + a)*HD + t] = accA[a] + ab;
            g_aj[(size_t)(bn0 + a)*HD + t] = accB[a];
        }
    }
}

// ---------------------------------------------------------------------------
// K3: graph attention + head.  16 i-rows per block, 128 threads.
// ---------------------------------------------------------------------------
__global__ void __launch_bounds__(128) graph_kernel(
    const float* __restrict__ adj,   const float* __restrict__ ga2_w,
    const float* __restrict__ ga2_b, const float* __restrict__ gout_w,
    const float* __restrict__ gout_b,const float* __restrict__ fc2_w,
    const float* __restrict__ fc2_b, float* __restrict__ out)
{
    const int b = blockIdx.x >> 4;
    const int i0 = (blockIdx.x & 15)*TI;
    const int t = threadIdx.x, lane = t & 31, warp = t >> 5;

    __shared__ __align__(16) float sAI[TI*HD];
    __shared__ __align__(16) float sBUF[4224];
    __shared__ __align__(16) float sE[TI*NA];
    __shared__ float sG2[HD];

    for (int idx = t; idx < TI*HD; idx += 128)
        sAI[idx] = g_ai[((size_t)(b*NA + i0))*HD + idx];
    sG2[t] = ga2_w[t];
    __syncthreads();

    const float g2b = ga2_b[0];
    const int jj = lane, iq = warp;
    for (int jc = 0; jc < NA; jc += 32) {
        __syncthreads();
        for (int idx = t; idx < 32*HD; idx += 128) {
            int r = idx >> 7, cc = idx & 127;
            sBUF[r*(HD+1) + cc] = g_aj[((size_t)(b*NA + jc))*HD + idx];
        }
        __syncthreads();
        float e0=0.f, e1=0.f, e2=0.f, e3=0.f;
        const float* aj = &sBUF[jj*(HD+1)];
        #pragma unroll 4
        for (int h = 0; h < HD; h++) {
            float v = aj[h], g = sG2[h];
            e0 += fmaxf(sAI[(iq     )*HD + h] + v, 0.f)*g;
            e1 += fmaxf(sAI[(iq + 4 )*HD + h] + v, 0.f)*g;
            e2 += fmaxf(sAI[(iq + 8 )*HD + h] + v, 0.f)*g;
            e3 += fmaxf(sAI[(iq + 12)*HD + h] + v, 0.f)*g;
        }
        sE[(iq     )*NA + jc + jj] = e0 + g2b;
        sE[(iq + 4 )*NA + jc + jj] = e1 + g2b;
        sE[(iq + 8 )*NA + jc + jj] = e2 + g2b;
        sE[(iq + 12)*NA + jc + jj] = e3 + g2b;
    }
    __syncthreads();

    for (int r = 0; r < 4; r++) {
        const int i = warp*4 + r;
        const float* adjr = adj + (size_t)(i0 + i)*NA;
        float pv[8]; float m = -3.4e38f;
        #pragma unroll
        for (int q = 0; q < 8; q++) {
            int j = lane + 32*q;
            float e = sE[i*NA + j];
            if (adjr[j] == 0.0f) e = -1e9f;
            pv[q] = e; m = fmaxf(m, e);
        }
        #pragma unroll
        for (int o = 16; o > 0; o >>= 1) m = fmaxf(m, __shfl_xor_sync(0xffffffffu, m, o));
        float s = 0.0f;
        #pragma unroll
        for (int q = 0; q < 8; q++) { pv[q] = expf(pv[q]-m); s += pv[q]; }
        #pragma unroll
        for (int o = 16; o > 0; o >>= 1) s += __shfl_xor_sync(0xffffffffu, s, o);
        const float inv = 1.0f/s;
        #pragma unroll
        for (int q = 0; q < 8; q++) sE[i*NA + lane + 32*q] = pv[q]*inv;
    }
    __syncthreads();

    float hp[TI];
    #pragma unroll
    for (int a = 0; a < TI; a++) hp[a] = 0.0f;
    for (int jc = 0; jc < NA; jc += 32) {
        __syncthreads();
        for (int idx = t; idx < 32*HD; idx += 128) {
            int r = idx >> 7, cc = idx & 127;
            sBUF[r*(HD+1) + cc] = g_hg[((size_t)(b*NA + jc))*HD + idx];
        }
        __syncthreads();
        for (int jr = 0; jr < 32; jr++) {
            float hv = sBUF[jr*(HD+1) + t];
            #pragma unroll
            for (int a = 0; a < TI; a++) hp[a] += sE[a*NA + jc + jr]*hv;
        }
    }
    __syncthreads();
    #pragma unroll
    for (int a = 0; a < TI; a++) sAI[a*HD + t] = hp[a];
    __syncthreads();

    {
        const float4* gw = (const float4*)(gout_w + (size_t)t*HD);
        float acc[TI];
        #pragma unroll
        for (int a = 0; a < TI; a++) acc[a] = 0.0f;
        #pragma unroll 2
        for (int k4 = 0; k4 < HD/4; k4++) {
            float4 w = gw[k4];
            #pragma unroll
            for (int a = 0; a < TI; a++) {
                float4 v = ((const float4*)&sAI[a*HD])[k4];
                acc[a] += v.x*w.x + v.y*w.y + v.z*w.z + v.w*w.w;
            }
        }
        const float gb = gout_b[t];
        #pragma unroll
        for (int a = 0; a < TI; a++) sE[a*132 + t] = acc[a] + gb;
    }
    for (int idx = t; idx < TI*HD; idx += 128) {
        int a = idx >> 7, k = idx & 127;
        sBUF[a*132 + k] = g_agg[((size_t)(b*NA + i0))*HD + idx];
    }
    for (int idx = t; idx < NACT*2*HD; idx += 128) {
        int act = idx >> 8, k = idx & 255;
        sBUF[TI*132 + act*257 + k] = fc2_w[idx];
    }
    __syncthreads();

    {
        const int a = t >> 3, act = t & 7;
        float acc = fc2_b[act];
        const float* sagg = &sBUF[a*132];
        const float* sw1  = &sBUF[TI*132 + act*257];
        const float* scm  = &sE[a*132];
        #pragma unroll 4
        for (int k = 0; k < HD; k++) acc += sagg[k]*sw1[k];
        #pragma unroll 4
        for (int k = 0; k < HD; k++) acc += scm[k]*sw1[HD + k];
        out[((size_t)(b*NA + i0 + a))*NACT + act] = acc;
    }
}

// ---------------------------------------------------------------------------
extern "C" void kernel_launch(void* const* d_in, const int* in_sizes, int n_in,
                              void* d_out, int out_size)
{
    const float* LF      = (const float*)d_in[0];
    const float* Hin     = (const float*)d_in[1];
    const float* adj     = (const float*)d_in[2];
    const float* fc1_w   = (const float*)d_in[3];
    const float* fc1_b   = (const float*)d_in[4];
    const float* w_ih    = (const float*)d_in[5];
    const float* w_hh    = (const float*)d_in[6];
    const float* b_ih    = (const float*)d_in[7];
    const float* b_hh    = (const float*)d_in[8];
    const float* lattn_w = (const float*)d_in[9];
    const float* lattn_b = (const float*)d_in[10];
    const float* gfc_w   = (const float*)d_in[11];
    const float* gfc_b   = (const float*)d_in[12];
    const float* ga1_w   = (const float*)d_in[13];
    const float* ga1_b   = (const float*)d_in[14];
    const float* ga2_w   = (const float*)d_in[15];
    const float* ga2_b   = (const float*)d_in[16];
    const float* gout_w  = (const float*)d_in[17];
    const float* gout_b  = (const float*)d_in[18];
    const float* fc2_w   = (const float*)d_in[19];
    const float* fc2_b   = (const float*)d_in[20];
    float* out = (float*)d_out;

    static int smem_set = 0;
    if (!smem_set) {
        cudaFuncSetAttribute(lane_kernel, cudaFuncAttributeMaxDynamicSharedMemorySize, SMEM_BYTES);
        smem_set = 1;
    }

    lane_kernel<<<LGRID, 256, SMEM_BYTES>>>(LF, Hin, fc1_w, fc1_b, w_ih, w_hh,
                                            b_ih, b_hh, lattn_w, lattn_b);
    node_kernel<<<BN/AG, 128>>>(gfc_w, gfc_b, ga1_w, ga1_b);
    graph_kernel<<<BSZ*(NA/TI), 128>>>(adj, ga2_w, ga2_b, gout_w, gout_b,
                                       fc2_w, fc2_b, out);
}